// round 4
// baseline (speedup 1.0000x reference)
#include <cuda_runtime.h>
#include <math.h>

// Problem constants (fixed shapes: x[16,2048,128], adj[16,2048,2048], W[128,128], bias[1,128])
#define B_DIM 16
#define N_DIM 2048
#define F_DIM 128
#define TR 64          // rows per block tile
#define TC 64          // cols per iteration tile
#define NEG_BIG (-9e15f)
#define LRELU_SLOPE 0.1f

// Scratch for xw = x @ W  (16 MB) — __device__ global (no allocation allowed)
__device__ float g_xw[(size_t)B_DIM * N_DIM * F_DIM];

// ---------------------------------------------------------------------------
// Kernel 1: xw[n,g] = sum_f x[n,f] * W[f,g]   (B*N = 32768 rows)
// One block = 16 rows, 128 threads (thread g owns output column g).
// ---------------------------------------------------------------------------
__global__ void __launch_bounds__(128) xw_kernel(const float* __restrict__ x,
                                                 const float* __restrict__ W)
{
    __shared__ float xs[16][F_DIM];
    const int row0 = blockIdx.x * 16;
    const int g = threadIdx.x;

    #pragma unroll
    for (int r = 0; r < 16; r++)
        xs[r][g] = x[(size_t)(row0 + r) * F_DIM + g];
    __syncthreads();

    float acc[16];
    #pragma unroll
    for (int r = 0; r < 16; r++) acc[r] = 0.f;

    #pragma unroll 4
    for (int f = 0; f < F_DIM; f++) {
        const float w = W[f * F_DIM + g];
        #pragma unroll
        for (int r = 0; r < 16; r++)
            acc[r] = fmaf(xs[r][f], w, acc[r]);
    }

    #pragma unroll
    for (int r = 0; r < 16; r++)
        g_xw[(size_t)(row0 + r) * F_DIM + g] = acc[r];
}

// ---------------------------------------------------------------------------
// Kernel 2: fused  sim -> leakyrelu -> mask -> online softmax -> attn@x -> +bias -> elu
//
// Block: (row-tile of 64, batch b). 256 threads as 16x16 (ty = tid/16, tx = tid%16).
// S phase: thread owns S[4x4] (rows ty*4.., cols tx*4..), f-major operands in smem.
// O phase: thread owns O[4 rows][8 f]  (f = tx*8..), P staged through smem.
//
// SMEM (floats):
//   xwT [128][68]  : xw tile transposed (f-major)   8704
//   xT  [128][68]  : x  tile transposed (f-major)   8704
//   xN  [ 64][132] : x  tile natural (m-major)      8448  (also staging for transposes)
//   pS  [ 64][68]  : softmax probs tile             4352
// ---------------------------------------------------------------------------
#define XWT_S 68
#define XT_S  68
#define XN_S  132
#define PS_S  68
#define OFF_XWT 0
#define OFF_XT  (128 * XWT_S)
#define OFF_XN  (OFF_XT + 128 * XT_S)
#define OFF_PS  (OFF_XN + 64 * XN_S)
#define SMEM_FLOATS (OFF_PS + 64 * PS_S)

__global__ void __launch_bounds__(256, 1) gat_kernel(
    const float* __restrict__ x,
    const int*   __restrict__ adj,
    const float* __restrict__ bias,
    float*       __restrict__ out)
{
    extern __shared__ float sm[];
    float* xwT = sm + OFF_XWT;
    float* xT  = sm + OFF_XT;
    float* xN  = sm + OFF_XN;
    float* pS  = sm + OFF_PS;

    const int b    = blockIdx.y;
    const int row0 = blockIdx.x * TR;
    const int tid  = threadIdx.x;
    const int ty   = tid >> 4;
    const int tx   = tid & 15;

    const float* xb   = x    + (size_t)b * N_DIM * F_DIM;
    const int*   adjb = adj  + (size_t)b * N_DIM * N_DIM;
    const float* xwb  = g_xw + (size_t)b * N_DIM * F_DIM;

    // ---- load xw row-tile (natural into xN staging), then transpose -> xwT
    #pragma unroll
    for (int it = 0; it < 8; it++) {
        int idx = it * 256 + tid;
        int r   = idx >> 5;            // 0..63
        int f4  = (idx & 31) << 2;     // 0..124
        float4 v = *reinterpret_cast<const float4*>(&xwb[(size_t)(row0 + r) * F_DIM + f4]);
        *reinterpret_cast<float4*>(&xN[r * XN_S + f4]) = v;
    }
    __syncthreads();
    #pragma unroll
    for (int it = 0; it < 8; it++) {
        int idx = it * 256 + tid;
        int f   = idx & 127;           // lane-consecutive f -> conflict-free column reads
        int mg  = idx >> 7;            // 0..15
        float4 v;
        v.x = xN[(mg * 4 + 0) * XN_S + f];
        v.y = xN[(mg * 4 + 1) * XN_S + f];
        v.z = xN[(mg * 4 + 2) * XN_S + f];
        v.w = xN[(mg * 4 + 3) * XN_S + f];
        *reinterpret_cast<float4*>(&xwT[f * XWT_S + mg * 4]) = v;
    }
    // (visibility of xwT is covered by the loop-top __syncthreads below)

    float O[4][8];
    #pragma unroll
    for (int i = 0; i < 4; i++)
        #pragma unroll
        for (int ff = 0; ff < 8; ff++) O[i][ff] = 0.f;

    float mrun[4], lrun[4];
    #pragma unroll
    for (int i = 0; i < 4; i++) { mrun[i] = -INFINITY; lrun[i] = 0.f; }

    for (int t = 0; t < N_DIM / TC; t++) {
        const int m0 = t * TC;

        __syncthreads();   // prev O-phase done reading xN/pS; t==0: xwT transpose done

        // ---- load x col-tile: natural -> xN
        #pragma unroll
        for (int it = 0; it < 8; it++) {
            int idx = it * 256 + tid;
            int m   = idx >> 5;
            int f4  = (idx & 31) << 2;
            float4 v = *reinterpret_cast<const float4*>(&xb[(size_t)(m0 + m) * F_DIM + f4]);
            *reinterpret_cast<float4*>(&xN[m * XN_S + f4]) = v;
        }
        __syncthreads();
        // ---- transpose xN -> xT (f-major)
        #pragma unroll
        for (int it = 0; it < 8; it++) {
            int idx = it * 256 + tid;
            int f   = idx & 127;
            int mg  = idx >> 7;
            float4 v;
            v.x = xN[(mg * 4 + 0) * XN_S + f];
            v.y = xN[(mg * 4 + 1) * XN_S + f];
            v.z = xN[(mg * 4 + 2) * XN_S + f];
            v.w = xN[(mg * 4 + 3) * XN_S + f];
            *reinterpret_cast<float4*>(&xT[f * XT_S + mg * 4]) = v;
        }

        // ---- prefetch adj (hides global latency under the sync + GEMM)
        int4 adjv[4];
        #pragma unroll
        for (int i = 0; i < 4; i++)
            adjv[i] = *reinterpret_cast<const int4*>(
                &adjb[(size_t)(row0 + ty * 4 + i) * N_DIM + m0 + tx * 4]);

        __syncthreads();   // xT visible

        // ---- S GEMM: c[i][j] = sum_f xw[r_i][f] * x[m_j][f]
        float c[4][4];
        #pragma unroll
        for (int i = 0; i < 4; i++)
            #pragma unroll
            for (int j = 0; j < 4; j++) c[i][j] = 0.f;

        #pragma unroll 4
        for (int f = 0; f < F_DIM; f++) {
            float4 a  = *reinterpret_cast<const float4*>(&xwT[f * XWT_S + ty * 4]);
            float4 bb = *reinterpret_cast<const float4*>(&xT [f * XT_S  + tx * 4]);
            float av[4] = {a.x, a.y, a.z, a.w};
            float bv[4] = {bb.x, bb.y, bb.z, bb.w};
            #pragma unroll
            for (int i = 0; i < 4; i++)
                #pragma unroll
                for (int j = 0; j < 4; j++)
                    c[i][j] = fmaf(av[i], bv[j], c[i][j]);
        }

        // ---- leaky relu + adjacency mask
        #pragma unroll
        for (int i = 0; i < 4; i++) {
            int am[4] = {adjv[i].x, adjv[i].y, adjv[i].z, adjv[i].w};
            #pragma unroll
            for (int j = 0; j < 4; j++) {
                float e = c[i][j];
                e = (e > 0.f) ? e : (LRELU_SLOPE * e);
                c[i][j] = (am[j] > 0) ? e : NEG_BIG;
            }
        }

        // ---- online softmax update (rows = ty*4+i; reduce across 16 tx lanes)
        #pragma unroll
        for (int i = 0; i < 4; i++) {
            float rm = fmaxf(fmaxf(c[i][0], c[i][1]), fmaxf(c[i][2], c[i][3]));
            rm = fmaxf(rm, __shfl_xor_sync(0xffffffffu, rm, 1));
            rm = fmaxf(rm, __shfl_xor_sync(0xffffffffu, rm, 2));
            rm = fmaxf(rm, __shfl_xor_sync(0xffffffffu, rm, 4));
            rm = fmaxf(rm, __shfl_xor_sync(0xffffffffu, rm, 8));

            float nm = fmaxf(mrun[i], rm);
            float sc = __expf(mrun[i] - nm);   // exp(-inf)=0 on first tile
            mrun[i] = nm;

            float rs = 0.f;
            #pragma unroll
            for (int j = 0; j < 4; j++) {
                c[i][j] = __expf(c[i][j] - nm);  // masked: exp(-9e15 - nm) -> 0
                rs += c[i][j];
            }
            rs += __shfl_xor_sync(0xffffffffu, rs, 1);
            rs += __shfl_xor_sync(0xffffffffu, rs, 2);
            rs += __shfl_xor_sync(0xffffffffu, rs, 4);
            rs += __shfl_xor_sync(0xffffffffu, rs, 8);

            lrun[i] = lrun[i] * sc + rs;

            #pragma unroll
            for (int ff = 0; ff < 8; ff++) O[i][ff] *= sc;
        }

        // ---- stage P tile to smem
        #pragma unroll
        for (int i = 0; i < 4; i++) {
            float4 pv = make_float4(c[i][0], c[i][1], c[i][2], c[i][3]);
            *reinterpret_cast<float4*>(&pS[(ty * 4 + i) * PS_S + tx * 4]) = pv;
        }
        __syncthreads();   // pS visible

        // ---- O GEMM: O[i][ff] += sum_m P[r_i][m] * x[m][tx*8+ff]
        #pragma unroll 2
        for (int m = 0; m < TC; m++) {
            float pv[4];
            #pragma unroll
            for (int i = 0; i < 4; i++)
                pv[i] = pS[(ty * 4 + i) * PS_S + m];

            const float* xr = &xN[m * XN_S + tx * 8];
            float4 xa = *reinterpret_cast<const float4*>(xr);
            float4 xc = *reinterpret_cast<const float4*>(xr + 4);
            float xv[8] = {xa.x, xa.y, xa.z, xa.w, xc.x, xc.y, xc.z, xc.w};

            #pragma unroll
            for (int i = 0; i < 4; i++)
                #pragma unroll
                for (int ff = 0; ff < 8; ff++)
                    O[i][ff] = fmaf(pv[i], xv[ff], O[i][ff]);
        }
    }

    // ---- epilogue: normalize, +bias, elu, store
    float4 b0 = *reinterpret_cast<const float4*>(&bias[tx * 8]);
    float4 b1 = *reinterpret_cast<const float4*>(&bias[tx * 8 + 4]);
    float bsv[8] = {b0.x, b0.y, b0.z, b0.w, b1.x, b1.y, b1.z, b1.w};

    #pragma unroll
    for (int i = 0; i < 4; i++) {
        const float inv = 1.0f / lrun[i];   // lrun >= 1 always (max element contributes 1)
        float h[8];
        #pragma unroll
        for (int ff = 0; ff < 8; ff++) {
            float v = O[i][ff] * inv + bsv[ff];
            h[ff] = (v > 0.f) ? v : expm1f(v);
        }
        const int row = row0 + ty * 4 + i;
        float* op = &out[((size_t)b * N_DIM + row) * F_DIM + tx * 8];
        *reinterpret_cast<float4*>(op)     = make_float4(h[0], h[1], h[2], h[3]);
        *reinterpret_cast<float4*>(op + 4) = make_float4(h[4], h[5], h[6], h[7]);
    }
}

// ---------------------------------------------------------------------------
// Launch. Inputs mapped by element count (all four sizes are unique):
//   x: 4194304 f32, adj: 67108864 i32, W_a: 16384 f32, bias: 128 f32
// ---------------------------------------------------------------------------
extern "C" void kernel_launch(void* const* d_in, const int* in_sizes, int n_in,
                              void* d_out, int out_size)
{
    const float* x  = nullptr;
    const int*   aj = nullptr;
    const float* W  = nullptr;
    const float* bi = nullptr;
    for (int i = 0; i < n_in; i++) {
        switch (in_sizes[i]) {
            case B_DIM * N_DIM * F_DIM: x  = (const float*)d_in[i]; break; // 4194304
            case 67108864:              aj = (const int*)  d_in[i]; break;
            case F_DIM * F_DIM:         W  = (const float*)d_in[i]; break; // 16384
            case F_DIM:                 bi = (const float*)d_in[i]; break; // 128
            default: break;
        }
    }
    float* out = (float*)d_out;

    const size_t smem_bytes = (size_t)SMEM_FLOATS * sizeof(float);  // 120832
    cudaFuncSetAttribute(gat_kernel, cudaFuncAttributeMaxDynamicSharedMemorySize,
                         (int)smem_bytes);

    xw_kernel<<<(B_DIM * N_DIM) / 16, 128>>>(x, W);

    dim3 grid(N_DIM / TR, B_DIM);   // (32, 16)
    gat_kernel<<<grid, 256, smem_bytes>>>(x, aj, bi, out);
}

// round 5
// speedup vs baseline: 1.4654x; 1.4654x over previous
#include <cuda_runtime.h>
#include <math.h>

// Fixed shapes: x[16,2048,128], adj[16,2048,2048], W[128,128], bias[1,128]
#define B_DIM 16
#define N_DIM 2048
#define F_DIM 128
#define TR 128         // rows per block tile
#define TC 128         // cols per iteration tile
#define NEG_BIG (-9e15f)
#define LRELU_SLOPE 0.1f

// Scratch for xw = x @ W (16 MB)
__device__ float g_xw[(size_t)B_DIM * N_DIM * F_DIM];

// ---------------------------------------------------------------------------
// Kernel 1: xw[n,g] = sum_f x[n,f] * W[f,g]
// ---------------------------------------------------------------------------
__global__ void __launch_bounds__(128) xw_kernel(const float* __restrict__ x,
                                                 const float* __restrict__ W)
{
    __shared__ float xs[16][F_DIM];
    const int row0 = blockIdx.x * 16;
    const int g = threadIdx.x;

    #pragma unroll
    for (int r = 0; r < 16; r++)
        xs[r][g] = x[(size_t)(row0 + r) * F_DIM + g];
    __syncthreads();

    float acc[16];
    #pragma unroll
    for (int r = 0; r < 16; r++) acc[r] = 0.f;

    #pragma unroll 4
    for (int f = 0; f < F_DIM; f++) {
        const float w = W[f * F_DIM + g];
        #pragma unroll
        for (int r = 0; r < 16; r++)
            acc[r] = fmaf(xs[r][f], w, acc[r]);
    }

    #pragma unroll
    for (int r = 0; r < 16; r++)
        g_xw[(size_t)(row0 + r) * F_DIM + g] = acc[r];
}

// ---------------------------------------------------------------------------
// Kernel 2: fused flash-style GAT. 128x128 tiles, 256 threads, 8x8 reg tiles.
//
// Thread grid: ty = tid/16 (0..15), tx = tid%16 (0..15).
//   S phase : rows r_i = ty*8+i (blocked 8), cols m_j = 4*tx + 64*jj + q
//             (two 4-wide groups, j = jj*4+q).
//   O phase : rows r_i = ty*8+i, f cols = [4*tx,4*tx+4) u [64+4*tx, 64+4*tx+4).
//
// SMEM: xwS [128][128] natural (64KB)
//       xS  [128][128] natural, 16B-unit XOR-swizzled by (m>>2)&7 (64KB)
//       pS  [128 r][136 m]  (69.6KB)
// ---------------------------------------------------------------------------
#define PS_S 136
#define OFF_XW 0
#define OFF_XS (128 * 128)
#define OFF_PS (2 * 128 * 128)
#define SMEM_FLOATS (2 * 128 * 128 + 128 * PS_S)

__global__ void __launch_bounds__(256, 1) gat_kernel(
    const float* __restrict__ x,
    const int*   __restrict__ adj,
    const float* __restrict__ bias,
    float*       __restrict__ out)
{
    extern __shared__ float sm[];
    float* xwS = sm + OFF_XW;
    float* xS  = sm + OFF_XS;
    float* pS  = sm + OFF_PS;
    float4* xwS4 = reinterpret_cast<float4*>(xwS);
    float4* xS4  = reinterpret_cast<float4*>(xS);

    const int b    = blockIdx.y;
    const int row0 = blockIdx.x * TR;
    const int tid  = threadIdx.x;
    const int ty   = tid >> 4;
    const int tx   = tid & 15;

    const float* xb   = x    + (size_t)b * N_DIM * F_DIM;
    const int*   adjb = adj  + (size_t)b * N_DIM * N_DIM;
    const float* xwb  = g_xw + (size_t)b * N_DIM * F_DIM;

    // ---- load xw row-tile: natural [r][f], row access only -> no swizzle
    #pragma unroll
    for (int it = 0; it < 16; it++) {
        int idx = it * 256 + tid;
        int r = idx >> 5;          // 0..127
        int u = idx & 31;          // 16B unit 0..31
        float4 v = *reinterpret_cast<const float4*>(&xwb[(size_t)(row0 + r) * F_DIM + u * 4]);
        xwS4[r * 32 + u] = v;
    }

    float O[8][8];
    #pragma unroll
    for (int i = 0; i < 8; i++)
        #pragma unroll
        for (int v = 0; v < 8; v++) O[i][v] = 0.f;

    float mrun[8], lrun[8];
    #pragma unroll
    for (int i = 0; i < 8; i++) { mrun[i] = -INFINITY; lrun[i] = 0.f; }

    // column ownership (S phase): m_j = 4*tx + 64*jj + q, swizzle key per col
    int mcol[8], msw[8];
    #pragma unroll
    for (int j = 0; j < 8; j++) {
        mcol[j] = 4 * tx + 64 * (j >> 2) + (j & 3);
        msw[j]  = (mcol[j] >> 2) & 7;
    }

    for (int t = 0; t < N_DIM / TC; t++) {
        const int m0 = t * TC;

        __syncthreads();   // prev O-GEMM done reading xS/pS; t==0: covers xwS too... (see below)

        // ---- load x col-tile, XOR-swizzled on (m>>2)&7
        #pragma unroll
        for (int it = 0; it < 16; it++) {
            int idx = it * 256 + tid;
            int m = idx >> 5;
            int u = idx & 31;
            float4 v = *reinterpret_cast<const float4*>(&xb[(size_t)(m0 + m) * F_DIM + u * 4]);
            xS4[m * 32 + (u ^ ((m >> 2) & 7))] = v;
        }
        __syncthreads();   // xS (and on t==0, xwS) visible

        // ---- S GEMM: c[i][j] = sum_f xw[r_i][f] * x[m_j][f]
        float c[8][8];
        #pragma unroll
        for (int i = 0; i < 8; i++)
            #pragma unroll
            for (int j = 0; j < 8; j++) c[i][j] = 0.f;

        #pragma unroll 2
        for (int f4 = 0; f4 < 32; f4++) {
            float4 a[8], bb[8];
            #pragma unroll
            for (int i = 0; i < 8; i++)
                a[i] = xwS4[(ty * 8 + i) * 32 + f4];
            #pragma unroll
            for (int j = 0; j < 8; j++)
                bb[j] = xS4[mcol[j] * 32 + (f4 ^ msw[j])];
            #pragma unroll
            for (int i = 0; i < 8; i++) {
                #pragma unroll
                for (int j = 0; j < 8; j++) {
                    c[i][j] = fmaf(a[i].x, bb[j].x, c[i][j]);
                    c[i][j] = fmaf(a[i].y, bb[j].y, c[i][j]);
                    c[i][j] = fmaf(a[i].z, bb[j].z, c[i][j]);
                    c[i][j] = fmaf(a[i].w, bb[j].w, c[i][j]);
                }
            }
        }

        // ---- adj prefetch: two coalesced int4 per row, straight to registers
        int4 aj[8][2];
        #pragma unroll
        for (int i = 0; i < 8; i++)
            #pragma unroll
            for (int jj = 0; jj < 2; jj++)
                aj[i][jj] = *reinterpret_cast<const int4*>(
                    &adjb[(size_t)(row0 + ty * 8 + i) * N_DIM + m0 + 4 * tx + 64 * jj]);

        // ---- leakyrelu + mask + online softmax (rows reduce across 16 tx lanes)
        #pragma unroll
        for (int i = 0; i < 8; i++) {
            int am[8] = {aj[i][0].x, aj[i][0].y, aj[i][0].z, aj[i][0].w,
                         aj[i][1].x, aj[i][1].y, aj[i][1].z, aj[i][1].w};
            float rmax = -INFINITY;
            #pragma unroll
            for (int j = 0; j < 8; j++) {
                float e = c[i][j];
                e = (e > 0.f) ? e : (LRELU_SLOPE * e);
                e = (am[j] > 0) ? e : NEG_BIG;
                c[i][j] = e;
                rmax = fmaxf(rmax, e);
            }
            rmax = fmaxf(rmax, __shfl_xor_sync(0xffffffffu, rmax, 8));
            rmax = fmaxf(rmax, __shfl_xor_sync(0xffffffffu, rmax, 4));
            rmax = fmaxf(rmax, __shfl_xor_sync(0xffffffffu, rmax, 2));
            rmax = fmaxf(rmax, __shfl_xor_sync(0xffffffffu, rmax, 1));

            float nm = fmaxf(mrun[i], rmax);
            float sc = __expf(mrun[i] - nm);   // exp(-inf)=0 on first tile
            mrun[i] = nm;

            float rs = 0.f;
            #pragma unroll
            for (int j = 0; j < 8; j++) {
                float p = __expf(c[i][j] - nm);
                c[i][j] = p;
                rs += p;
            }
            rs += __shfl_xor_sync(0xffffffffu, rs, 8);
            rs += __shfl_xor_sync(0xffffffffu, rs, 4);
            rs += __shfl_xor_sync(0xffffffffu, rs, 2);
            rs += __shfl_xor_sync(0xffffffffu, rs, 1);

            lrun[i] = lrun[i] * sc + rs;

            #pragma unroll
            for (int v = 0; v < 8; v++) O[i][v] *= sc;
        }

        // ---- store P -> pS [r][m], float4 along the 4-wide q groups
        #pragma unroll
        for (int i = 0; i < 8; i++) {
            #pragma unroll
            for (int jj = 0; jj < 2; jj++) {
                float4 pv = make_float4(c[i][jj * 4 + 0], c[i][jj * 4 + 1],
                                        c[i][jj * 4 + 2], c[i][jj * 4 + 3]);
                *reinterpret_cast<float4*>(
                    &pS[(ty * 8 + i) * PS_S + 4 * tx + 64 * jj]) = pv;
            }
        }
        __syncthreads();   // pS visible

        // ---- O GEMM: O[i][v] += P[r_i][m] * x[m][f_v]
        #pragma unroll 2
        for (int m = 0; m < TC; m++) {
            const int s = (m >> 2) & 7;
            float4 b0 = xS4[m * 32 + (tx ^ s)];
            float4 b1 = xS4[m * 32 + ((tx ^ s) + 16)];
            float bv[8] = {b0.x, b0.y, b0.z, b0.w, b1.x, b1.y, b1.z, b1.w};

            float av[8];
            #pragma unroll
            for (int i = 0; i < 8; i++)
                av[i] = pS[(ty * 8 + i) * PS_S + m];

            #pragma unroll
            for (int i = 0; i < 8; i++)
                #pragma unroll
                for (int v = 0; v < 8; v++)
                    O[i][v] = fmaf(av[i], bv[v], O[i][v]);
        }
    }

    // ---- epilogue: normalize, +bias, elu, store (f = 4tx.. and 64+4tx..)
    float4 bias0 = *reinterpret_cast<const float4*>(&bias[4 * tx]);
    float4 bias1 = *reinterpret_cast<const float4*>(&bias[64 + 4 * tx]);
    float bsv[8] = {bias0.x, bias0.y, bias0.z, bias0.w,
                    bias1.x, bias1.y, bias1.z, bias1.w};

    #pragma unroll
    for (int i = 0; i < 8; i++) {
        const float inv = 1.0f / lrun[i];
        float h[8];
        #pragma unroll
        for (int v = 0; v < 8; v++) {
            float val = O[i][v] * inv + bsv[v];
            h[v] = (val > 0.f) ? val : expm1f(val);
        }
        const int row = row0 + ty * 8 + i;
        float* op = &out[((size_t)b * N_DIM + row) * F_DIM];
        *reinterpret_cast<float4*>(op + 4 * tx)      = make_float4(h[0], h[1], h[2], h[3]);
        *reinterpret_cast<float4*>(op + 64 + 4 * tx) = make_float4(h[4], h[5], h[6], h[7]);
    }
}

// ---------------------------------------------------------------------------
// Launch. Inputs mapped by element count (all four are unique):
//   x: 4194304 f32, adj: 67108864 i32, W_a: 16384 f32, bias: 128 f32
// ---------------------------------------------------------------------------
extern "C" void kernel_launch(void* const* d_in, const int* in_sizes, int n_in,
                              void* d_out, int out_size)
{
    const float* x  = nullptr;
    const int*   aj = nullptr;
    const float* W  = nullptr;
    const float* bi = nullptr;
    for (int i = 0; i < n_in; i++) {
        switch (in_sizes[i]) {
            case B_DIM * N_DIM * F_DIM: x  = (const float*)d_in[i]; break; // 4194304
            case 67108864:              aj = (const int*)  d_in[i]; break;
            case F_DIM * F_DIM:         W  = (const float*)d_in[i]; break; // 16384
            case F_DIM:                 bi = (const float*)d_in[i]; break; // 128
            default: break;
        }
    }
    float* out = (float*)d_out;

    const size_t smem_bytes = (size_t)SMEM_FLOATS * sizeof(float);  // 200704
    cudaFuncSetAttribute(gat_kernel, cudaFuncAttributeMaxDynamicSharedMemorySize,
                         (int)smem_bytes);

    xw_kernel<<<(B_DIM * N_DIM) / 16, 128>>>(x, W);

    dim3 grid(N_DIM / TR, B_DIM);   // (16, 16) = 256 blocks
    gat_kernel<<<grid, 256, smem_bytes>>>(x, aj, bi, out);
}

// round 7
// speedup vs baseline: 3.3642x; 2.2957x over previous
#include <cuda_runtime.h>
#include <cuda_bf16.h>
#include <math.h>
#include <stdint.h>

// Fixed shapes: x[16,2048,128], adj[16,2048,2048], W[128,128], bias[1,128]
#define B_DIM 16
#define N_DIM 2048
#define F_DIM 128
#define NEG_BIG (-9e15f)
#define NELEM ((size_t)B_DIM * N_DIM * F_DIM)   // 4194304

// ---------------- device scratch (no allocation allowed) -------------------
__device__ __align__(256) float         g_xw  [NELEM];
__device__ __align__(256) __nv_bfloat16 g_xw_h[NELEM];
__device__ __align__(256) __nv_bfloat16 g_xw_l[NELEM];
__device__ __align__(256) __nv_bfloat16 g_x_h [NELEM];
__device__ __align__(256) __nv_bfloat16 g_x_l [NELEM];

// ---------------- PTX helpers (sm_80+ features only: valid on sm_100 base) -
__device__ __forceinline__ uint32_t smem_u32(const void* p) {
    uint32_t a;
    asm("{ .reg .u64 t; cvta.to.shared.u64 t, %1; cvt.u32.u64 %0, t; }"
        : "=r"(a) : "l"(p));
    return a;
}
__device__ __forceinline__ void cp16(uint32_t saddr, const void* gaddr) {
    asm volatile("cp.async.cg.shared.global [%0], [%1], 16;"
                 :: "r"(saddr), "l"(gaddr));
}
#define CP_COMMIT() asm volatile("cp.async.commit_group;" ::: "memory")
#define CP_WAIT1()  asm volatile("cp.async.wait_group 1;"  ::: "memory")
#define CP_WAIT0()  asm volatile("cp.async.wait_group 0;"  ::: "memory")

__device__ __forceinline__ void ldsm4(uint32_t* r, uint32_t addr) {
    asm volatile("ldmatrix.sync.aligned.m8n8.x4.shared.b16 {%0,%1,%2,%3}, [%4];"
                 : "=r"(r[0]), "=r"(r[1]), "=r"(r[2]), "=r"(r[3]) : "r"(addr));
}
__device__ __forceinline__ void ldsm4t(uint32_t* r, uint32_t addr) {
    asm volatile("ldmatrix.sync.aligned.m8n8.x4.trans.shared.b16 {%0,%1,%2,%3}, [%4];"
                 : "=r"(r[0]), "=r"(r[1]), "=r"(r[2]), "=r"(r[3]) : "r"(addr));
}
// D += A*B  (m16n8k16, row.col, bf16 in, f32 accum)
__device__ __forceinline__ void mma16816(float* d, const uint32_t* a, const uint32_t* b) {
    asm volatile("mma.sync.aligned.m16n8k16.row.col.f32.bf16.bf16.f32 "
        "{%0,%1,%2,%3}, {%4,%5,%6,%7}, {%8,%9}, {%0,%1,%2,%3};"
        : "+f"(d[0]), "+f"(d[1]), "+f"(d[2]), "+f"(d[3])
        : "r"(a[0]), "r"(a[1]), "r"(a[2]), "r"(a[3]), "r"(b[0]), "r"(b[1]));
}

// ---------------- SMEM layout (bytes). Tiles: [128 rows][128 bf16] = 32KB,
// row = 256B = 16x 16B units, unit swizzle u ^= (row & 7). -------------------
#define TILE_B   32768
#define SM_XWH   0
#define SM_XWL   32768
#define SM_XB(buf) (65536 + (buf) * 65536)   // x_h at +0, x_l at +32768
#define SM_TOTAL 196608

// ---------------------------------------------------------------------------
// Prep 1: xw = x @ W (fp32)
// ---------------------------------------------------------------------------
__global__ void __launch_bounds__(128) xw_kernel(const float* __restrict__ x,
                                                 const float* __restrict__ W)
{
    __shared__ float xs[16][F_DIM];
    const int row0 = blockIdx.x * 16;
    const int g = threadIdx.x;
    #pragma unroll
    for (int r = 0; r < 16; r++)
        xs[r][g] = x[(size_t)(row0 + r) * F_DIM + g];
    __syncthreads();
    float acc[16];
    #pragma unroll
    for (int r = 0; r < 16; r++) acc[r] = 0.f;
    #pragma unroll 4
    for (int f = 0; f < F_DIM; f++) {
        const float w = W[f * F_DIM + g];
        #pragma unroll
        for (int r = 0; r < 16; r++) acc[r] = fmaf(xs[r][f], w, acc[r]);
    }
    #pragma unroll
    for (int r = 0; r < 16; r++)
        g_xw[(size_t)(row0 + r) * F_DIM + g] = acc[r];
}

// ---------------------------------------------------------------------------
// Prep 2: bf16 hi/lo split of x and xw
// ---------------------------------------------------------------------------
__device__ __forceinline__ void split2(float a, float b, uint32_t& hi, uint32_t& lo) {
    __nv_bfloat16 ha = __float2bfloat16(a), hb = __float2bfloat16(b);
    __nv_bfloat16 la = __float2bfloat16(a - __bfloat162float(ha));
    __nv_bfloat16 lb = __float2bfloat16(b - __bfloat162float(hb));
    hi = ((uint32_t)__bfloat16_as_ushort(hb) << 16) | __bfloat16_as_ushort(ha);
    lo = ((uint32_t)__bfloat16_as_ushort(lb) << 16) | __bfloat16_as_ushort(la);
}

__global__ void __launch_bounds__(256) conv_kernel(const float* __restrict__ x)
{
    size_t i4 = (size_t)blockIdx.x * 256 + threadIdx.x;
    float4 xv = *reinterpret_cast<const float4*>(x + i4 * 4);
    float4 wv = *reinterpret_cast<const float4*>(g_xw + i4 * 4);
    uint2 xh, xl, wh, wl;
    split2(xv.x, xv.y, xh.x, xl.x);  split2(xv.z, xv.w, xh.y, xl.y);
    split2(wv.x, wv.y, wh.x, wl.x);  split2(wv.z, wv.w, wh.y, wl.y);
    reinterpret_cast<uint2*>(g_x_h )[i4] = xh;
    reinterpret_cast<uint2*>(g_x_l )[i4] = xl;
    reinterpret_cast<uint2*>(g_xw_h)[i4] = wh;
    reinterpret_cast<uint2*>(g_xw_l)[i4] = wl;
}

// ---------------------------------------------------------------------------
// Main fused kernel. Block = 128-row tile of one batch. 8 warps x 16 rows.
// 3-term bf16 HMMA for S = XW@X^T and O += P@X; flash-style online softmax
// with P kept in registers (C-fragment -> A-fragment repack).
// ---------------------------------------------------------------------------
__global__ void __launch_bounds__(256, 1) gat_mma_kernel(
    const int*   __restrict__ adj,
    const float* __restrict__ bias,
    float*       __restrict__ out)
{
    extern __shared__ char sm[];
    const uint32_t sb = smem_u32(sm);

    const int b    = blockIdx.y;
    const int row0 = blockIdx.x * 128;
    const int tid  = threadIdx.x;
    const int lane = tid & 31;
    const int w    = tid >> 5;
    const int g    = lane >> 2;        // mma group row
    const int t4   = lane & 3;         // mma group col
    const int wrow0 = w * 16;          // warp's row base within tile
    const int mat  = lane >> 3;        // ldmatrix lane roles
    const int rr   = lane & 7;

    const char* xwh_g = (const char*)(g_xw_h + ((size_t)b * N_DIM + row0) * F_DIM);
    const char* xwl_g = (const char*)(g_xw_l + ((size_t)b * N_DIM + row0) * F_DIM);
    const char* xh_g  = (const char*)(g_x_h  + (size_t)b * N_DIM * F_DIM);
    const char* xl_g  = (const char*)(g_x_l  + (size_t)b * N_DIM * F_DIM);
    const int*  adjb  = adj + (size_t)b * N_DIM * N_DIM + (size_t)row0 * N_DIM;

    // ---- prologue: cp.async xw tiles + x tile 0 (buf 0)
    #pragma unroll
    for (int k = 0; k < 8; k++) {
        int uu  = k * 256 + tid;
        int row = uu >> 4, u = uu & 15;
        uint32_t so = (uint32_t)row * 256 + ((u ^ (row & 7)) << 4);
        size_t   go = (size_t)row * 256 + u * 16;
        cp16(sb + SM_XWH + so,   xwh_g + go);
        cp16(sb + SM_XWL + so,   xwl_g + go);
        cp16(sb + SM_XB(0) + so,           xh_g + go);
        cp16(sb + SM_XB(0) + TILE_B + so,  xl_g + go);
    }
    CP_COMMIT();

    float o[16][4];
    #pragma unroll
    for (int nt = 0; nt < 16; nt++)
        #pragma unroll
        for (int q = 0; q < 4; q++) o[nt][q] = 0.f;
    float m0r = -INFINITY, m1r = -INFINITY, l0r = 0.f, l1r = 0.f;

    for (int t = 0; t < 16; t++) {
        const int mbase = t * 128;

        // ---- adjacency bitmasks for this warp's two rows (g, g+8), via ballot
        uint32_t mk0[4], mk1[4];
        #pragma unroll
        for (int rw = 0; rw < 16; rw++) {
            #pragma unroll
            for (int wd = 0; wd < 4; wd++) {
                int v = adjb[(size_t)(wrow0 + rw) * N_DIM + mbase + wd * 32 + lane];
                uint32_t msk = __ballot_sync(0xffffffffu, v > 0);
                if (rw == g)     mk0[wd] = msk;
                if (rw == g + 8) mk1[wd] = msk;
            }
        }

        __syncthreads();               // everyone done reading buf^1 (prev iter)
        if (t < 15) {                  // prefetch next x tile into buf^1
            const char* nh = xh_g + (size_t)(t + 1) * 128 * 256;
            const char* nl = xl_g + (size_t)(t + 1) * 128 * 256;
            uint32_t dst = sb + SM_XB((t + 1) & 1);
            #pragma unroll
            for (int k = 0; k < 8; k++) {
                int uu = k * 256 + tid;
                int row = uu >> 4, u = uu & 15;
                uint32_t so = (uint32_t)row * 256 + ((u ^ (row & 7)) << 4);
                size_t   go = (size_t)row * 256 + u * 16;
                cp16(dst + so,          nh + go);
                cp16(dst + TILE_B + so, nl + go);
            }
            CP_COMMIT();
            CP_WAIT1();
        } else {
            CP_WAIT0();
        }
        __syncthreads();               // current tile visible to all

        const uint32_t xb = sb + SM_XB(t & 1);   // x_h base; x_l = +TILE_B

        // ---- S-GEMM: c[nt] (m16n8 frags), 3 bf16 terms, k = f (128)
        float c[16][4];
        #pragma unroll
        for (int nt = 0; nt < 16; nt++)
            #pragma unroll
            for (int q = 0; q < 4; q++) c[nt][q] = 0.f;

        #pragma unroll
        for (int s = 0; s < 8; s++) {
            // A frag: xw rows (row-major [m][k]) -> ldsm x4 non-trans
            int arow = wrow0 + rr + ((mat & 1) << 3);
            int au   = 2 * s + (mat >> 1);
            uint32_t aaddr = sb + SM_XWH + (uint32_t)arow * 256 + ((au ^ (arow & 7)) << 4);
            uint32_t ah[4], al[4];
            ldsm4(ah, aaddr);
            ldsm4(al, aaddr + TILE_B);
            #pragma unroll
            for (int np = 0; np < 8; np++) {
                // B frag: x rows j ([n][k] row-major) -> ldsm x4 non-trans (TN)
                int brow = np * 16 + rr + ((mat >> 1) << 3);
                int bu   = 2 * s + (mat & 1);
                uint32_t baddr = xb + (uint32_t)brow * 256 + ((bu ^ (brow & 7)) << 4);
                uint32_t bh[4], bl[4];
                ldsm4(bh, baddr);
                ldsm4(bl, baddr + TILE_B);
                mma16816(c[2 * np],     ah, &bh[0]);
                mma16816(c[2 * np],     ah, &bl[0]);
                mma16816(c[2 * np],     al, &bh[0]);
                mma16816(c[2 * np + 1], ah, &bh[2]);
                mma16816(c[2 * np + 1], ah, &bl[2]);
                mma16816(c[2 * np + 1], al, &bh[2]);
            }
        }

        // ---- leakyrelu + mask + online softmax (rows g / g+8)
        float rmax0 = -INFINITY, rmax1 = -INFINITY;
        #pragma unroll
        for (int nt = 0; nt < 16; nt++) {
            uint32_t w0 = mk0[nt >> 2], w1 = mk1[nt >> 2];
            int bsh = ((nt & 3) << 3) + 2 * t4;
            float e;
            e = fmaxf(c[nt][0], 0.1f * c[nt][0]);
            e = ((w0 >> bsh) & 1u) ? e : NEG_BIG; c[nt][0] = e; rmax0 = fmaxf(rmax0, e);
            e = fmaxf(c[nt][1], 0.1f * c[nt][1]);
            e = ((w0 >> (bsh + 1)) & 1u) ? e : NEG_BIG; c[nt][1] = e; rmax0 = fmaxf(rmax0, e);
            e = fmaxf(c[nt][2], 0.1f * c[nt][2]);
            e = ((w1 >> bsh) & 1u) ? e : NEG_BIG; c[nt][2] = e; rmax1 = fmaxf(rmax1, e);
            e = fmaxf(c[nt][3], 0.1f * c[nt][3]);
            e = ((w1 >> (bsh + 1)) & 1u) ? e : NEG_BIG; c[nt][3] = e; rmax1 = fmaxf(rmax1, e);
        }
        rmax0 = fmaxf(rmax0, __shfl_xor_sync(0xffffffffu, rmax0, 1));
        rmax0 = fmaxf(rmax0, __shfl_xor_sync(0xffffffffu, rmax0, 2));
        rmax1 = fmaxf(rmax1, __shfl_xor_sync(0xffffffffu, rmax1, 1));
        rmax1 = fmaxf(rmax1, __shfl_xor_sync(0xffffffffu, rmax1, 2));

        float nm0 = fmaxf(m0r, rmax0), nm1 = fmaxf(m1r, rmax1);
        float sc0 = (nm0 == -INFINITY) ? 0.f : __expf(m0r - nm0);
        float sc1 = (nm1 == -INFINITY) ? 0.f : __expf(m1r - nm1);
        m0r = nm0; m1r = nm1;

        float rs0 = 0.f, rs1 = 0.f;
        uint32_t ph[16][2], pl[16][2];   // P frags (hi/lo), rows g / g+8
        #pragma unroll
        for (int nt = 0; nt < 16; nt++) {
            float p0 = __expf(c[nt][0] - nm0);   // masked NEG_BIG -> underflow 0
            float p1 = __expf(c[nt][1] - nm0);
            float p2 = __expf(c[nt][2] - nm1);
            float p3 = __expf(c[nt][3] - nm1);
            rs0 += p0 + p1; rs1 += p2 + p3;
            split2(p0, p1, ph[nt][0], pl[nt][0]);
            split2(p2, p3, ph[nt][1], pl[nt][1]);
        }
        rs0 += __shfl_xor_sync(0xffffffffu, rs0, 1);
        rs0 += __shfl_xor_sync(0xffffffffu, rs0, 2);
        rs1 += __shfl_xor_sync(0xffffffffu, rs1, 1);
        rs1 += __shfl_xor_sync(0xffffffffu, rs1, 2);
        l0r = l0r * sc0 + rs0;
        l1r = l1r * sc1 + rs1;

        #pragma unroll
        for (int nt = 0; nt < 16; nt++) {
            o[nt][0] *= sc0; o[nt][1] *= sc0;
            o[nt][2] *= sc1; o[nt][3] *= sc1;
        }

        // ---- O-GEMM: O += P @ X ; A = P frags (regs), B = x via ldsm.trans
        #pragma unroll
        for (int s = 0; s < 8; s++) {
            uint32_t aH[4] = {ph[2*s][0], ph[2*s][1], ph[2*s+1][0], ph[2*s+1][1]};
            uint32_t aL[4] = {pl[2*s][0], pl[2*s][1], pl[2*s+1][0], pl[2*s+1][1]};
            #pragma unroll
            for (int np = 0; np < 8; np++) {
                int brow = s * 16 + rr + ((mat & 1) << 3);   // k = m rows
                int bu   = 2 * np + (mat >> 1);              // n = f cols
                uint32_t baddr = xb + (uint32_t)brow * 256 + ((bu ^ (brow & 7)) << 4);
                uint32_t bh[4], bl[4];
                ldsm4t(bh, baddr);
                ldsm4t(bl, baddr + TILE_B);
                mma16816(o[2 * np],     aH, &bh[0]);
                mma16816(o[2 * np],     aH, &bl[0]);
                mma16816(o[2 * np],     aL, &bh[0]);
                mma16816(o[2 * np + 1], aH, &bh[2]);
                mma16816(o[2 * np + 1], aH, &bl[2]);
                mma16816(o[2 * np + 1], aL, &bh[2]);
            }
        }
    }

    // ---- epilogue: normalize, +bias, elu, store
    const float inv0 = 1.f / l0r, inv1 = 1.f / l1r;
    const int gr0 = row0 + wrow0 + g;
    float* outb = out + (size_t)b * N_DIM * F_DIM;
    #pragma unroll
    for (int nt = 0; nt < 16; nt++) {
        int f = nt * 8 + 2 * t4;
        float bb0 = __ldg(&bias[f]), bb1 = __ldg(&bias[f + 1]);
        float v0 = o[nt][0] * inv0 + bb0; v0 = (v0 > 0.f) ? v0 : expm1f(v0);
        float v1 = o[nt][1] * inv0 + bb1; v1 = (v1 > 0.f) ? v1 : expm1f(v1);
        float v2 = o[nt][2] * inv1 + bb0; v2 = (v2 > 0.f) ? v2 : expm1f(v2);
        float v3 = o[nt][3] * inv1 + bb1; v3 = (v3 > 0.f) ? v3 : expm1f(v3);
        *reinterpret_cast<float2*>(&outb[(size_t)gr0 * F_DIM + f])       = make_float2(v0, v1);
        *reinterpret_cast<float2*>(&outb[(size_t)(gr0 + 8) * F_DIM + f]) = make_float2(v2, v3);
    }
}

// ---------------------------------------------------------------------------
// Launch. Inputs mapped by element count (all four unique):
//   x: 4194304 f32, adj: 67108864 i32, W_a: 16384 f32, bias: 128 f32
// ---------------------------------------------------------------------------
extern "C" void kernel_launch(void* const* d_in, const int* in_sizes, int n_in,
                              void* d_out, int out_size)
{
    (void)out_size;
    const float* x  = nullptr;
    const int*   aj = nullptr;
    const float* W  = nullptr;
    const float* bi = nullptr;
    for (int i = 0; i < n_in; i++) {
        switch (in_sizes[i]) {
            case (int)NELEM:    x  = (const float*)d_in[i]; break;  // 4194304
            case 67108864:      aj = (const int*)  d_in[i]; break;
            case F_DIM * F_DIM: W  = (const float*)d_in[i]; break;  // 16384
            case F_DIM:         bi = (const float*)d_in[i]; break;  // 128
            default: break;
        }
    }
    float* out = (float*)d_out;

    xw_kernel<<<(B_DIM * N_DIM) / 16, 128>>>(x, W);
    conv_kernel<<<(int)(NELEM / 4 / 256), 256>>>(x);

    cudaFuncSetAttribute(gat_mma_kernel, cudaFuncAttributeMaxDynamicSharedMemorySize,
                         SM_TOTAL);
    dim3 grid(N_DIM / 128, B_DIM);   // (16, 16) = 256 blocks
    gat_mma_kernel<<<grid, 256, SM_TOTAL>>>(aj, bi, out);
}

// round 8
// speedup vs baseline: 3.4613x; 1.0289x over previous
#include <cuda_runtime.h>
#include <cuda_bf16.h>
#include <math.h>
#include <stdint.h>

// Fixed shapes: x[16,2048,128], adj[16,2048,2048], W[128,128], bias[1,128]
#define B_DIM 16
#define N_DIM 2048
#define F_DIM 128
#define NEG_BIG (-9e15f)
#define NELEM ((size_t)B_DIM * N_DIM * F_DIM)   // 4194304

// ---------------- device scratch (no allocation allowed) -------------------
__device__ __align__(256) __nv_bfloat16 g_xw_h[NELEM];
__device__ __align__(256) __nv_bfloat16 g_xw_l[NELEM];
__device__ __align__(256) __nv_bfloat16 g_x_h [NELEM];
__device__ __align__(256) __nv_bfloat16 g_x_l [NELEM];

// ---------------- PTX helpers (sm_80+ features only: valid on sm_100 base) -
__device__ __forceinline__ uint32_t smem_u32(const void* p) {
    uint32_t a;
    asm("{ .reg .u64 t; cvta.to.shared.u64 t, %1; cvt.u32.u64 %0, t; }"
        : "=r"(a) : "l"(p));
    return a;
}
__device__ __forceinline__ void cp16(uint32_t saddr, const void* gaddr) {
    asm volatile("cp.async.cg.shared.global [%0], [%1], 16;"
                 :: "r"(saddr), "l"(gaddr));
}
#define CP_COMMIT() asm volatile("cp.async.commit_group;" ::: "memory")
#define CP_WAIT1()  asm volatile("cp.async.wait_group 1;"  ::: "memory")
#define CP_WAIT0()  asm volatile("cp.async.wait_group 0;"  ::: "memory")

__device__ __forceinline__ void ldsm4(uint32_t* r, uint32_t addr) {
    asm volatile("ldmatrix.sync.aligned.m8n8.x4.shared.b16 {%0,%1,%2,%3}, [%4];"
                 : "=r"(r[0]), "=r"(r[1]), "=r"(r[2]), "=r"(r[3]) : "r"(addr));
}
__device__ __forceinline__ void ldsm4t(uint32_t* r, uint32_t addr) {
    asm volatile("ldmatrix.sync.aligned.m8n8.x4.trans.shared.b16 {%0,%1,%2,%3}, [%4];"
                 : "=r"(r[0]), "=r"(r[1]), "=r"(r[2]), "=r"(r[3]) : "r"(addr));
}
// D += A*B  (m16n8k16, row.col, bf16 in, f32 accum)
__device__ __forceinline__ void mma16816(float* d, const uint32_t* a, const uint32_t* b) {
    asm volatile("mma.sync.aligned.m16n8k16.row.col.f32.bf16.bf16.f32 "
        "{%0,%1,%2,%3}, {%4,%5,%6,%7}, {%8,%9}, {%0,%1,%2,%3};"
        : "+f"(d[0]), "+f"(d[1]), "+f"(d[2]), "+f"(d[3])
        : "r"(a[0]), "r"(a[1]), "r"(a[2]), "r"(a[3]), "r"(b[0]), "r"(b[1]));
}

// packed bf16 hi/lo split of a float pair (6 instrs)
__device__ __forceinline__ void split2(float a, float b, uint32_t& hi, uint32_t& lo) {
    uint32_t h;
    asm("cvt.rn.bf16x2.f32 %0, %1, %2;" : "=r"(h) : "f"(b), "f"(a));
    float ha = __uint_as_float(h << 16);
    float hb = __uint_as_float(h & 0xffff0000u);
    float la = a - ha, lb = b - hb;
    uint32_t l;
    asm("cvt.rn.bf16x2.f32 %0, %1, %2;" : "=r"(l) : "f"(lb), "f"(la));
    hi = h; lo = l;
}

// ---------------- SMEM layouts ----------------------------------------------
// main kernel tiles: [128 rows][128 bf16] = 32KB, row = 256B = 16x 16B units,
// unit swizzle u ^= (row & 7).
#define TILE_B   32768
#define SM_XWH   0
#define SM_XWL   32768
#define SM_XB(buf) (65536 + (buf) * 65536)   // x_h at +0, x_l at +32768
#define SM_TOTAL 196608

// prep kernel: Wt [128 g][140 f] fp32 (stride 140 -> 16B aligned, conflict-free
// float4 reads; region reused as xw staging [64 r][128 g]) + xs [64 r][128 f]
#define WT_S      140
#define PREP_XS   (128 * WT_S)                         // float offset of xs
#define PREP_SMEM ((128 * WT_S + 64 * 128) * 4)        // 104448 bytes

// ---------------------------------------------------------------------------
// Fused prep: per block = 64 rows of (b,n).
//   1. load W -> smem transposed Wt[g][f]
//   2. load x rows -> smem + write bf16 hi/lo splits of x (from registers)
//   3. xw = x @ W (fp32, W from smem: fma-bound)
//   4. stage xw in smem (reusing Wt), split -> g_xw_h / g_xw_l
// ---------------------------------------------------------------------------
__global__ void __launch_bounds__(256, 2) prep_kernel(const float* __restrict__ x,
                                                      const float* __restrict__ W)
{
    extern __shared__ float ps[];
    float*  Wt  = ps;
    float*  xs  = ps + PREP_XS;
    float4* xs4 = reinterpret_cast<float4*>(xs);

    const int tid  = threadIdx.x;
    const int row0 = blockIdx.x * 64;

    // ---- W transposed into smem
    #pragma unroll
    for (int it = 0; it < 16; it++) {
        int idx4 = it * 256 + tid;
        int f  = idx4 >> 5;          // 0..127
        int g4 = (idx4 & 31) * 4;    // 0..124
        float4 wv = *reinterpret_cast<const float4*>(&W[f * F_DIM + g4]);
        Wt[(g4 + 0) * WT_S + f] = wv.x;
        Wt[(g4 + 1) * WT_S + f] = wv.y;
        Wt[(g4 + 2) * WT_S + f] = wv.z;
        Wt[(g4 + 3) * WT_S + f] = wv.w;
    }

    // ---- x rows -> smem; split x -> global (coalesced uint2 stores)
    #pragma unroll
    for (int it = 0; it < 8; it++) {
        int idx = it * 256 + tid;
        int r = idx >> 5, u = idx & 31;
        float4 v = *reinterpret_cast<const float4*>(&x[(size_t)(row0 + r) * F_DIM + u * 4]);
        xs4[r * 32 + u] = v;
        uint2 h, l;
        split2(v.x, v.y, h.x, l.x);
        split2(v.z, v.w, h.y, l.y);
        size_t o4 = (size_t)(row0 + r) * 32 + u;
        reinterpret_cast<uint2*>(g_x_h)[o4] = h;
        reinterpret_cast<uint2*>(g_x_l)[o4] = l;
    }
    __syncthreads();

    // ---- GEMM: thread = (col g, row-half h2); 32 rows per thread
    const int g  = tid & 127;
    const int r0 = (tid >> 7) * 32;
    float acc[32];
    #pragma unroll
    for (int r = 0; r < 32; r++) acc[r] = 0.f;

    #pragma unroll 4
    for (int f4 = 0; f4 < 32; f4++) {
        float4 w4 = *reinterpret_cast<const float4*>(&Wt[g * WT_S + f4 * 4]);
        #pragma unroll
        for (int r = 0; r < 32; r++) {
            float4 xv = xs4[(r0 + r) * 32 + f4];   // warp-uniform -> broadcast
            acc[r] = fmaf(xv.x, w4.x, acc[r]);
            acc[r] = fmaf(xv.y, w4.y, acc[r]);
            acc[r] = fmaf(xv.z, w4.z, acc[r]);
            acc[r] = fmaf(xv.w, w4.w, acc[r]);
        }
    }
    __syncthreads();                 // all Wt reads done

    // ---- stage xw (reuse Wt region), then split -> global
    #pragma unroll
    for (int r = 0; r < 32; r++)
        ps[(r0 + r) * 128 + g] = acc[r];
    __syncthreads();

    #pragma unroll
    for (int it = 0; it < 8; it++) {
        int idx = it * 256 + tid;
        int r = idx >> 5, u = idx & 31;
        float4 v = *reinterpret_cast<const float4*>(&ps[r * 128 + u * 4]);
        uint2 h, l;
        split2(v.x, v.y, h.x, l.x);
        split2(v.z, v.w, h.y, l.y);
        size_t o4 = (size_t)(row0 + r) * 32 + u;
        reinterpret_cast<uint2*>(g_xw_h)[o4] = h;
        reinterpret_cast<uint2*>(g_xw_l)[o4] = l;
    }
}

// ---------------------------------------------------------------------------
// Main fused kernel. Block = 128-row tile of one batch. 8 warps x 16 rows.
// 3-term bf16 HMMA for S = XW@X^T and O += P@X; flash-style online softmax
// with P kept in registers (C-fragment -> A-fragment repack).
// ---------------------------------------------------------------------------
__global__ void __launch_bounds__(256, 1) gat_mma_kernel(
    const int*   __restrict__ adj,
    const float* __restrict__ bias,
    float*       __restrict__ out)
{
    extern __shared__ char sm[];
    const uint32_t sb = smem_u32(sm);

    const int b    = blockIdx.y;
    const int row0 = blockIdx.x * 128;
    const int tid  = threadIdx.x;
    const int lane = tid & 31;
    const int w    = tid >> 5;
    const int g    = lane >> 2;        // mma group row
    const int t4   = lane & 3;         // mma group col
    const int wrow0 = w * 16;          // warp's row base within tile
    const int mat  = lane >> 3;        // ldmatrix lane roles
    const int rr   = lane & 7;

    const char* xwh_g = (const char*)(g_xw_h + ((size_t)b * N_DIM + row0) * F_DIM);
    const char* xwl_g = (const char*)(g_xw_l + ((size_t)b * N_DIM + row0) * F_DIM);
    const char* xh_g  = (const char*)(g_x_h  + (size_t)b * N_DIM * F_DIM);
    const char* xl_g  = (const char*)(g_x_l  + (size_t)b * N_DIM * F_DIM);
    const int*  adjb  = adj + (size_t)b * N_DIM * N_DIM + (size_t)row0 * N_DIM;

    // ---- prologue: cp.async xw tiles + x tile 0 (buf 0)
    #pragma unroll
    for (int k = 0; k < 8; k++) {
        int uu  = k * 256 + tid;
        int row = uu >> 4, u = uu & 15;
        uint32_t so = (uint32_t)row * 256 + ((u ^ (row & 7)) << 4);
        size_t   go = (size_t)row * 256 + u * 16;
        cp16(sb + SM_XWH + so,   xwh_g + go);
        cp16(sb + SM_XWL + so,   xwl_g + go);
        cp16(sb + SM_XB(0) + so,           xh_g + go);
        cp16(sb + SM_XB(0) + TILE_B + so,  xl_g + go);
    }
    CP_COMMIT();

    float o[16][4];
    #pragma unroll
    for (int nt = 0; nt < 16; nt++)
        #pragma unroll
        for (int q = 0; q < 4; q++) o[nt][q] = 0.f;
    float m0r = -INFINITY, m1r = -INFINITY, l0r = 0.f, l1r = 0.f;

    for (int t = 0; t < 16; t++) {
        const int mbase = t * 128;

        // ---- adjacency bitmasks for this warp's two rows (g, g+8), via ballot
        uint32_t mk0[4], mk1[4];
        #pragma unroll
        for (int rw = 0; rw < 16; rw++) {
            #pragma unroll
            for (int wd = 0; wd < 4; wd++) {
                int v = adjb[(size_t)(wrow0 + rw) * N_DIM + mbase + wd * 32 + lane];
                uint32_t msk = __ballot_sync(0xffffffffu, v > 0);
                if (rw == g)     mk0[wd] = msk;
                if (rw == g + 8) mk1[wd] = msk;
            }
        }

        __syncthreads();               // everyone done reading buf^1 (prev iter)
        if (t < 15) {                  // prefetch next x tile into buf^1
            const char* nh = xh_g + (size_t)(t + 1) * 128 * 256;
            const char* nl = xl_g + (size_t)(t + 1) * 128 * 256;
            uint32_t dst = sb + SM_XB((t + 1) & 1);
            #pragma unroll
            for (int k = 0; k < 8; k++) {
                int uu = k * 256 + tid;
                int row = uu >> 4, u = uu & 15;
                uint32_t so = (uint32_t)row * 256 + ((u ^ (row & 7)) << 4);
                size_t   go = (size_t)row * 256 + u * 16;
                cp16(dst + so,          nh + go);
                cp16(dst + TILE_B + so, nl + go);
            }
            CP_COMMIT();
            CP_WAIT1();
        } else {
            CP_WAIT0();
        }
        __syncthreads();               // current tile visible to all

        const uint32_t xb = sb + SM_XB(t & 1);   // x_h base; x_l = +TILE_B

        // ---- S-GEMM: c[nt] (m16n8 frags), 3 bf16 terms, k = f (128)
        float c[16][4];
        #pragma unroll
        for (int nt = 0; nt < 16; nt++)
            #pragma unroll
            for (int q = 0; q < 4; q++) c[nt][q] = 0.f;

        #pragma unroll
        for (int s = 0; s < 8; s++) {
            // A frag: xw rows (row-major [m][k]) -> ldsm x4 non-trans
            int arow = wrow0 + rr + ((mat & 1) << 3);
            int au   = 2 * s + (mat >> 1);
            uint32_t aaddr = sb + SM_XWH + (uint32_t)arow * 256 + ((au ^ (arow & 7)) << 4);
            uint32_t ah[4], al[4];
            ldsm4(ah, aaddr);
            ldsm4(al, aaddr + TILE_B);
            #pragma unroll
            for (int np = 0; np < 8; np++) {
                // B frag: x rows j ([n][k] row-major) -> ldsm x4 non-trans (TN)
                int brow = np * 16 + rr + ((mat >> 1) << 3);
                int bu   = 2 * s + (mat & 1);
                uint32_t baddr = xb + (uint32_t)brow * 256 + ((bu ^ (brow & 7)) << 4);
                uint32_t bh[4], bl[4];
                ldsm4(bh, baddr);
                ldsm4(bl, baddr + TILE_B);
                mma16816(c[2 * np],     ah, &bh[0]);
                mma16816(c[2 * np],     ah, &bl[0]);
                mma16816(c[2 * np],     al, &bh[0]);
                mma16816(c[2 * np + 1], ah, &bh[2]);
                mma16816(c[2 * np + 1], ah, &bl[2]);
                mma16816(c[2 * np + 1], al, &bh[2]);
            }
        }

        // ---- leakyrelu + mask + online softmax (rows g / g+8)
        float rmax0 = -INFINITY, rmax1 = -INFINITY;
        #pragma unroll
        for (int nt = 0; nt < 16; nt++) {
            uint32_t w0 = mk0[nt >> 2], w1 = mk1[nt >> 2];
            int bsh = ((nt & 3) << 3) + 2 * t4;
            float e;
            e = fmaxf(c[nt][0], 0.1f * c[nt][0]);
            e = ((w0 >> bsh) & 1u) ? e : NEG_BIG; c[nt][0] = e; rmax0 = fmaxf(rmax0, e);
            e = fmaxf(c[nt][1], 0.1f * c[nt][1]);
            e = ((w0 >> (bsh + 1)) & 1u) ? e : NEG_BIG; c[nt][1] = e; rmax0 = fmaxf(rmax0, e);
            e = fmaxf(c[nt][2], 0.1f * c[nt][2]);
            e = ((w1 >> bsh) & 1u) ? e : NEG_BIG; c[nt][2] = e; rmax1 = fmaxf(rmax1, e);
            e = fmaxf(c[nt][3], 0.1f * c[nt][3]);
            e = ((w1 >> (bsh + 1)) & 1u) ? e : NEG_BIG; c[nt][3] = e; rmax1 = fmaxf(rmax1, e);
        }
        rmax0 = fmaxf(rmax0, __shfl_xor_sync(0xffffffffu, rmax0, 1));
        rmax0 = fmaxf(rmax0, __shfl_xor_sync(0xffffffffu, rmax0, 2));
        rmax1 = fmaxf(rmax1, __shfl_xor_sync(0xffffffffu, rmax1, 1));
        rmax1 = fmaxf(rmax1, __shfl_xor_sync(0xffffffffu, rmax1, 2));

        float nm0 = fmaxf(m0r, rmax0), nm1 = fmaxf(m1r, rmax1);
        float sc0 = (nm0 == -INFINITY) ? 0.f : __expf(m0r - nm0);
        float sc1 = (nm1 == -INFINITY) ? 0.f : __expf(m1r - nm1);
        m0r = nm0; m1r = nm1;

        float rs0 = 0.f, rs1 = 0.f;
        uint32_t ph[16][2], pl[16][2];   // P frags (hi/lo), rows g / g+8
        #pragma unroll
        for (int nt = 0; nt < 16; nt++) {
            float p0 = __expf(c[nt][0] - nm0);   // masked NEG_BIG -> underflow 0
            float p1 = __expf(c[nt][1] - nm0);
            float p2 = __expf(c[nt][2] - nm1);
            float p3 = __expf(c[nt][3] - nm1);
            rs0 += p0 + p1; rs1 += p2 + p3;
            split2(p0, p1, ph[nt][0], pl[nt][0]);
            split2(p2, p3, ph[nt][1], pl[nt][1]);
        }
        rs0 += __shfl_xor_sync(0xffffffffu, rs0, 1);
        rs0 += __shfl_xor_sync(0xffffffffu, rs0, 2);
        rs1 += __shfl_xor_sync(0xffffffffu, rs1, 1);
        rs1 += __shfl_xor_sync(0xffffffffu, rs1, 2);
        l0r = l0r * sc0 + rs0;
        l1r = l1r * sc1 + rs1;

        #pragma unroll
        for (int nt = 0; nt < 16; nt++) {
            o[nt][0] *= sc0; o[nt][1] *= sc0;
            o[nt][2] *= sc1; o[nt][3] *= sc1;
        }

        // ---- O-GEMM: O += P @ X ; A = P frags (regs), B = x via ldsm.trans
        #pragma unroll
        for (int s = 0; s < 8; s++) {
            uint32_t aH[4] = {ph[2*s][0], ph[2*s][1], ph[2*s+1][0], ph[2*s+1][1]};
            uint32_t aL[4] = {pl[2*s][0], pl[2*s][1], pl[2*s+1][0], pl[2*s+1][1]};
            #pragma unroll
            for (int np = 0; np < 8; np++) {
                int brow = s * 16 + rr + ((mat & 1) << 3);   // k = m rows
                int bu   = 2 * np + (mat >> 1);              // n = f cols
                uint32_t baddr = xb + (uint32_t)brow * 256 + ((bu ^ (brow & 7)) << 4);
                uint32_t bh[4], bl[4];
                ldsm4t(bh, baddr);
                ldsm4t(bl, baddr + TILE_B);
                mma16816(o[2 * np],     aH, &bh[0]);
                mma16816(o[2 * np],     aH, &bl[0]);
                mma16816(o[2 * np],     aL, &bh[0]);
                mma16816(o[2 * np + 1], aH, &bh[2]);
                mma16816(o[2 * np + 1], aH, &bl[2]);
                mma16816(o[2 * np + 1], aL, &bh[2]);
            }
        }
    }

    // ---- epilogue: normalize, +bias, elu, store
    const float inv0 = 1.f / l0r, inv1 = 1.f / l1r;
    const int gr0 = row0 + wrow0 + g;
    float* outb = out + (size_t)b * N_DIM * F_DIM;
    #pragma unroll
    for (int nt = 0; nt < 16; nt++) {
        int f = nt * 8 + 2 * t4;
        float bb0 = __ldg(&bias[f]), bb1 = __ldg(&bias[f + 1]);
        float v0 = o[nt][0] * inv0 + bb0; v0 = (v0 > 0.f) ? v0 : expm1f(v0);
        float v1 = o[nt][1] * inv0 + bb1; v1 = (v1 > 0.f) ? v1 : expm1f(v1);
        float v2 = o[nt][2] * inv1 + bb0; v2 = (v2 > 0.f) ? v2 : expm1f(v2);
        float v3 = o[nt][3] * inv1 + bb1; v3 = (v3 > 0.f) ? v3 : expm1f(v3);
        *reinterpret_cast<float2*>(&outb[(size_t)gr0 * F_DIM + f])       = make_float2(v0, v1);
        *reinterpret_cast<float2*>(&outb[(size_t)(gr0 + 8) * F_DIM + f]) = make_float2(v2, v3);
    }
}

// ---------------------------------------------------------------------------
// Launch. Inputs mapped by element count (all four unique):
//   x: 4194304 f32, adj: 67108864 i32, W_a: 16384 f32, bias: 128 f32
// ---------------------------------------------------------------------------
extern "C" void kernel_launch(void* const* d_in, const int* in_sizes, int n_in,
                              void* d_out, int out_size)
{
    (void)out_size;
    const float* x  = nullptr;
    const int*   aj = nullptr;
    const float* W  = nullptr;
    const float* bi = nullptr;
    for (int i = 0; i < n_in; i++) {
        switch (in_sizes[i]) {
            case (int)NELEM:    x  = (const float*)d_in[i]; break;  // 4194304
            case 67108864:      aj = (const int*)  d_in[i]; break;
            case F_DIM * F_DIM: W  = (const float*)d_in[i]; break;  // 16384
            case F_DIM:         bi = (const float*)d_in[i]; break;  // 128
            default: break;
        }
    }
    float* out = (float*)d_out;

    cudaFuncSetAttribute(prep_kernel, cudaFuncAttributeMaxDynamicSharedMemorySize,
                         PREP_SMEM);
    prep_kernel<<<(B_DIM * N_DIM) / 64, 256, PREP_SMEM>>>(x, W);

    cudaFuncSetAttribute(gat_mma_kernel, cudaFuncAttributeMaxDynamicSharedMemorySize,
                         SM_TOTAL);
    dim3 grid(N_DIM / 128, B_DIM);   // (16, 16) = 256 blocks
    gat_mma_kernel<<<grid, 256, SM_TOTAL>>>(aj, bi, out);
}

// round 9
// speedup vs baseline: 4.0647x; 1.1743x over previous
#include <cuda_runtime.h>
#include <cuda_bf16.h>
#include <math.h>
#include <stdint.h>

// Fixed shapes: x[16,2048,128], adj[16,2048,2048], W[128,128], bias[1,128]
#define B_DIM 16
#define N_DIM 2048
#define F_DIM 128
#define NEG_BIG (-9e15f)
#define NELEM ((size_t)B_DIM * N_DIM * F_DIM)   // 4194304

// ---------------- device scratch (no allocation allowed) -------------------
__device__ __align__(256) __nv_bfloat16 g_x_h [NELEM];
__device__ __align__(256) __nv_bfloat16 g_x_l [NELEM];
__device__ __align__(256) __nv_bfloat16 g_wt_h[F_DIM * F_DIM];   // W^T [g][f]
__device__ __align__(256) __nv_bfloat16 g_wt_l[F_DIM * F_DIM];

// ---------------- PTX helpers (sm_80+ features only) ------------------------
__device__ __forceinline__ uint32_t smem_u32(const void* p) {
    uint32_t a;
    asm("{ .reg .u64 t; cvta.to.shared.u64 t, %1; cvt.u32.u64 %0, t; }"
        : "=r"(a) : "l"(p));
    return a;
}
__device__ __forceinline__ void cp16(uint32_t saddr, const void* gaddr) {
    asm volatile("cp.async.cg.shared.global [%0], [%1], 16;"
                 :: "r"(saddr), "l"(gaddr));
}
#define CP_COMMIT() asm volatile("cp.async.commit_group;" ::: "memory")
#define CP_WAIT1()  asm volatile("cp.async.wait_group 1;"  ::: "memory")
#define CP_WAIT0()  asm volatile("cp.async.wait_group 0;"  ::: "memory")

__device__ __forceinline__ void ldsm4(uint32_t* r, uint32_t addr) {
    asm volatile("ldmatrix.sync.aligned.m8n8.x4.shared.b16 {%0,%1,%2,%3}, [%4];"
                 : "=r"(r[0]), "=r"(r[1]), "=r"(r[2]), "=r"(r[3]) : "r"(addr));
}
__device__ __forceinline__ void ldsm4t(uint32_t* r, uint32_t addr) {
    asm volatile("ldmatrix.sync.aligned.m8n8.x4.trans.shared.b16 {%0,%1,%2,%3}, [%4];"
                 : "=r"(r[0]), "=r"(r[1]), "=r"(r[2]), "=r"(r[3]) : "r"(addr));
}
// D += A*B  (m16n8k16, row.col, bf16 in, f32 accum)
__device__ __forceinline__ void mma16816(float* d, const uint32_t* a, const uint32_t* b) {
    asm volatile("mma.sync.aligned.m16n8k16.row.col.f32.bf16.bf16.f32 "
        "{%0,%1,%2,%3}, {%4,%5,%6,%7}, {%8,%9}, {%0,%1,%2,%3};"
        : "+f"(d[0]), "+f"(d[1]), "+f"(d[2]), "+f"(d[3])
        : "r"(a[0]), "r"(a[1]), "r"(a[2]), "r"(a[3]), "r"(b[0]), "r"(b[1]));
}

// packed bf16 hi/lo split of a float pair
__device__ __forceinline__ void split2(float a, float b, uint32_t& hi, uint32_t& lo) {
    uint32_t h;
    asm("cvt.rn.bf16x2.f32 %0, %1, %2;" : "=r"(h) : "f"(b), "f"(a));
    float ha = __uint_as_float(h << 16);
    float hb = __uint_as_float(h & 0xffff0000u);
    float la = a - ha, lb = b - hb;
    uint32_t l;
    asm("cvt.rn.bf16x2.f32 %0, %1, %2;" : "=r"(l) : "f"(lb), "f"(la));
    hi = h; lo = l;
}

// ---------------- SMEM layout -----------------------------------------------
// tiles: [128 rows][128 bf16] = 32KB, row = 256B = 16x 16B units,
// unit swizzle u ^= (row & 7).
#define TILE_B   32768
#define SM_XWH   0
#define SM_XWL   32768
#define SM_XB(buf) (65536 + (buf) * 65536)   // hi at +0, lo at +32768
#define SM_TOTAL 196608

// ---------------------------------------------------------------------------
// Prep A: W^T bf16 hi/lo split:  g_wt[g][f] = split(W[f][g])
// ---------------------------------------------------------------------------
__global__ void __launch_bounds__(256) wsplit_kernel(const float* __restrict__ W)
{
    int idx = blockIdx.x * 256 + threadIdx.x;      // 0..16383
    int g = idx >> 7, f = idx & 127;
    float v = W[f * F_DIM + g];
    __nv_bfloat16 h = __float2bfloat16(v);
    __nv_bfloat16 l = __float2bfloat16(v - __bfloat162float(h));
    g_wt_h[idx] = h;                               // [g][f] row-major
    g_wt_l[idx] = l;
}

// ---------------------------------------------------------------------------
// Prep B: x bf16 hi/lo split (pure memory pass)
// ---------------------------------------------------------------------------
__global__ void __launch_bounds__(256) xsplit_kernel(const float* __restrict__ x)
{
    size_t i4 = (size_t)blockIdx.x * 256 + threadIdx.x;
    float4 v = *reinterpret_cast<const float4*>(x + i4 * 4);
    uint2 h, l;
    split2(v.x, v.y, h.x, l.x);
    split2(v.z, v.w, h.y, l.y);
    reinterpret_cast<uint2*>(g_x_h)[i4] = h;
    reinterpret_cast<uint2*>(g_x_l)[i4] = l;
}

// ---------------------------------------------------------------------------
// Main fused kernel. Block = 128-row tile of one batch. 8 warps x 16 rows.
// Prologue: xw tile = x_rows @ W via 3-term HMMA, split -> smem (A operand).
// Loop: 3-term HMMA S = XW@X^T -> mask/online-softmax -> 3-term HMMA O += P@X,
// P split inline from C-fragments (no persistent P arrays).
// ---------------------------------------------------------------------------
__global__ void __launch_bounds__(256, 1) gat_mma_kernel(
    const int*   __restrict__ adj,
    const float* __restrict__ bias,
    float*       __restrict__ out)
{
    extern __shared__ char sm[];
    const uint32_t sb = smem_u32(sm);

    const int b    = blockIdx.y;
    const int row0 = blockIdx.x * 128;
    const int tid  = threadIdx.x;
    const int lane = tid & 31;
    const int w    = tid >> 5;
    const int g    = lane >> 2;        // mma group row
    const int t4   = lane & 3;         // mma group col
    const int wrow0 = w * 16;          // warp's row base within tile
    const int mat  = lane >> 3;        // ldmatrix lane roles
    const int rr   = lane & 7;
    const int t4h  = t4 >> 1;          // mask lane-index component
    const int t4e  = t4 & 1;           // mask word-pair select

    const char* xh_g  = (const char*)(g_x_h + (size_t)b * N_DIM * F_DIM);
    const char* xl_g  = (const char*)(g_x_l + (size_t)b * N_DIM * F_DIM);
    const char* xh_r0 = xh_g + (size_t)row0 * 256;   // this block's own rows
    const char* xl_r0 = xl_g + (size_t)row0 * 256;
    const int*  adjb  = adj + (size_t)b * N_DIM * N_DIM + (size_t)row0 * N_DIM;

    // ======== prologue: compute xw tile via HMMA ========
    // load x rows (A) into XB(0), W^T (B) into XB(1)
    #pragma unroll
    for (int k = 0; k < 8; k++) {
        int uu  = k * 256 + tid;
        int row = uu >> 4, u = uu & 15;
        uint32_t so = (uint32_t)row * 256 + ((u ^ (row & 7)) << 4);
        size_t   go = (size_t)row * 256 + u * 16;
        cp16(sb + SM_XB(0) + so,          xh_r0 + go);
        cp16(sb + SM_XB(0) + TILE_B + so, xl_r0 + go);
        cp16(sb + SM_XB(1) + so,          (const char*)g_wt_h + go);
        cp16(sb + SM_XB(1) + TILE_B + so, (const char*)g_wt_l + go);
    }
    CP_COMMIT();
    CP_WAIT0();
    __syncthreads();

    {
        float cw[16][4];
        #pragma unroll
        for (int nt = 0; nt < 16; nt++)
            #pragma unroll
            for (int q = 0; q < 4; q++) cw[nt][q] = 0.f;

        #pragma unroll
        for (int s = 0; s < 8; s++) {
            int arow = wrow0 + rr + ((mat & 1) << 3);
            int au   = 2 * s + (mat >> 1);
            uint32_t aaddr = sb + SM_XB(0) + (uint32_t)arow * 256 + ((au ^ (arow & 7)) << 4);
            uint32_t ah[4], al[4];
            ldsm4(ah, aaddr);
            ldsm4(al, aaddr + TILE_B);
            #pragma unroll
            for (int np = 0; np < 8; np++) {
                int brow = np * 16 + rr + ((mat >> 1) << 3);
                int bu   = 2 * s + (mat & 1);
                uint32_t baddr = sb + SM_XB(1) + (uint32_t)brow * 256 + ((bu ^ (brow & 7)) << 4);
                uint32_t bh[4], bl[4];
                ldsm4(bh, baddr);
                ldsm4(bl, baddr + TILE_B);
                mma16816(cw[2 * np],     ah, &bh[0]);
                mma16816(cw[2 * np],     ah, &bl[0]);
                mma16816(cw[2 * np],     al, &bh[0]);
                mma16816(cw[2 * np + 1], ah, &bh[2]);
                mma16816(cw[2 * np + 1], ah, &bl[2]);
                mma16816(cw[2 * np + 1], al, &bh[2]);
            }
        }

        // split C-frags -> xw hi/lo smem tiles (same swizzled layout)
        const int r0a = wrow0 + g, r1a = r0a + 8;
        #pragma unroll
        for (int nt = 0; nt < 16; nt++) {
            uint32_t h01, l01, h23, l23;
            split2(cw[nt][0], cw[nt][1], h01, l01);
            split2(cw[nt][2], cw[nt][3], h23, l23);
            uint32_t off0 = (uint32_t)r0a * 256 + ((nt ^ (r0a & 7)) << 4) + 4 * t4;
            uint32_t off1 = (uint32_t)r1a * 256 + ((nt ^ (r1a & 7)) << 4) + 4 * t4;
            *reinterpret_cast<uint32_t*>(sm + SM_XWH + off0) = h01;
            *reinterpret_cast<uint32_t*>(sm + SM_XWL + off0) = l01;
            *reinterpret_cast<uint32_t*>(sm + SM_XWH + off1) = h23;
            *reinterpret_cast<uint32_t*>(sm + SM_XWL + off1) = l23;
        }
    }
    __syncthreads();          // xw visible; XB(0)/XB(1) reads done everywhere

    // prefetch x tile 0 into XB(0)
    #pragma unroll
    for (int k = 0; k < 8; k++) {
        int uu  = k * 256 + tid;
        int row = uu >> 4, u = uu & 15;
        uint32_t so = (uint32_t)row * 256 + ((u ^ (row & 7)) << 4);
        size_t   go = (size_t)row * 256 + u * 16;
        cp16(sb + SM_XB(0) + so,          xh_g + go);
        cp16(sb + SM_XB(0) + TILE_B + so, xl_g + go);
    }
    CP_COMMIT();

    float o[16][4];
    #pragma unroll
    for (int nt = 0; nt < 16; nt++)
        #pragma unroll
        for (int q = 0; q < 4; q++) o[nt][q] = 0.f;
    float m0r = -INFINITY, m1r = -INFINITY, l0r = 0.f, l1r = 0.f;

    for (int t = 0; t < 16; t++) {
        const int mbase = t * 128;

        // ---- batched adj prefetch: one int4 per (row) -> regs
        int4 ajv[16];
        #pragma unroll
        for (int rw = 0; rw < 16; rw++)
            ajv[rw] = *reinterpret_cast<const int4*>(
                &adjb[(size_t)(wrow0 + rw) * N_DIM + mbase + 4 * lane]);

        __syncthreads();               // buf (t+1)&1 readers (tile t-1) done
        if (t < 15) {                  // prefetch next x tile into buf^1
            const char* nh = xh_g + (size_t)(t + 1) * 128 * 256;
            const char* nl = xl_g + (size_t)(t + 1) * 128 * 256;
            uint32_t dst = sb + SM_XB((t + 1) & 1);
            #pragma unroll
            for (int k = 0; k < 8; k++) {
                int uu = k * 256 + tid;
                int row = uu >> 4, u = uu & 15;
                uint32_t so = (uint32_t)row * 256 + ((u ^ (row & 7)) << 4);
                size_t   go = (size_t)row * 256 + u * 16;
                cp16(dst + so,          nh + go);
                cp16(dst + TILE_B + so, nl + go);
            }
            CP_COMMIT();
        }

        // ---- ballots: word c bit lane <-> col 4*lane+c; keep 2 words per row
        uint32_t wE0, wO0, wE1, wO1;
        #pragma unroll
        for (int rw = 0; rw < 16; rw++) {
            uint32_t b0 = __ballot_sync(0xffffffffu, ajv[rw].x > 0);
            uint32_t b1 = __ballot_sync(0xffffffffu, ajv[rw].y > 0);
            uint32_t b2 = __ballot_sync(0xffffffffu, ajv[rw].z > 0);
            uint32_t b3 = __ballot_sync(0xffffffffu, ajv[rw].w > 0);
            uint32_t be = t4e ? b2 : b0;
            uint32_t bo = t4e ? b3 : b1;
            if (rw == g)     { wE0 = be; wO0 = bo; }
            if (rw == g + 8) { wE1 = be; wO1 = bo; }
        }

        if (t < 15) CP_WAIT1(); else CP_WAIT0();
        __syncthreads();               // current tile visible to all

        const uint32_t xb = sb + SM_XB(t & 1);   // x_h base; x_l = +TILE_B

        // ---- S-GEMM: c[nt] (m16n8 frags), 3 bf16 terms, k = f (128)
        float c[16][4];
        #pragma unroll
        for (int nt = 0; nt < 16; nt++)
            #pragma unroll
            for (int q = 0; q < 4; q++) c[nt][q] = 0.f;

        #pragma unroll
        for (int s = 0; s < 8; s++) {
            int arow = wrow0 + rr + ((mat & 1) << 3);
            int au   = 2 * s + (mat >> 1);
            uint32_t aaddr = sb + SM_XWH + (uint32_t)arow * 256 + ((au ^ (arow & 7)) << 4);
            uint32_t ah[4], al[4];
            ldsm4(ah, aaddr);
            ldsm4(al, aaddr + TILE_B);
            #pragma unroll
            for (int np = 0; np < 8; np++) {
                int brow = np * 16 + rr + ((mat >> 1) << 3);
                int bu   = 2 * s + (mat & 1);
                uint32_t baddr = xb + (uint32_t)brow * 256 + ((bu ^ (brow & 7)) << 4);
                uint32_t bh[4], bl[4];
                ldsm4(bh, baddr);
                ldsm4(bl, baddr + TILE_B);
                mma16816(c[2 * np],     ah, &bh[0]);
                mma16816(c[2 * np],     ah, &bl[0]);
                mma16816(c[2 * np],     al, &bh[0]);
                mma16816(c[2 * np + 1], ah, &bh[2]);
                mma16816(c[2 * np + 1], ah, &bl[2]);
                mma16816(c[2 * np + 1], al, &bh[2]);
            }
        }

        // ---- leakyrelu + mask + online softmax (rows g / g+8)
        float rmax0 = -INFINITY, rmax1 = -INFINITY;
        #pragma unroll
        for (int nt = 0; nt < 16; nt++) {
            int ln = 2 * nt + t4h;     // bit index: col>>2
            float e;
            e = fmaxf(c[nt][0], 0.1f * c[nt][0]);
            e = ((wE0 >> ln) & 1u) ? e : NEG_BIG; c[nt][0] = e; rmax0 = fmaxf(rmax0, e);
            e = fmaxf(c[nt][1], 0.1f * c[nt][1]);
            e = ((wO0 >> ln) & 1u) ? e : NEG_BIG; c[nt][1] = e; rmax0 = fmaxf(rmax0, e);
            e = fmaxf(c[nt][2], 0.1f * c[nt][2]);
            e = ((wE1 >> ln) & 1u) ? e : NEG_BIG; c[nt][2] = e; rmax1 = fmaxf(rmax1, e);
            e = fmaxf(c[nt][3], 0.1f * c[nt][3]);
            e = ((wO1 >> ln) & 1u) ? e : NEG_BIG; c[nt][3] = e; rmax1 = fmaxf(rmax1, e);
        }
        rmax0 = fmaxf(rmax0, __shfl_xor_sync(0xffffffffu, rmax0, 1));
        rmax0 = fmaxf(rmax0, __shfl_xor_sync(0xffffffffu, rmax0, 2));
        rmax1 = fmaxf(rmax1, __shfl_xor_sync(0xffffffffu, rmax1, 1));
        rmax1 = fmaxf(rmax1, __shfl_xor_sync(0xffffffffu, rmax1, 2));

        float nm0 = fmaxf(m0r, rmax0), nm1 = fmaxf(m1r, rmax1);
        float sc0 = (nm0 == -INFINITY) ? 0.f : __expf(m0r - nm0);
        float sc1 = (nm1 == -INFINITY) ? 0.f : __expf(m1r - nm1);
        m0r = nm0; m1r = nm1;

        float rs0 = 0.f, rs1 = 0.f;
        #pragma unroll
        for (int nt = 0; nt < 16; nt++) {        // c becomes P in place
            float p0 = __expf(c[nt][0] - nm0);   // masked NEG_BIG -> 0
            float p1 = __expf(c[nt][1] - nm0);
            float p2 = __expf(c[nt][2] - nm1);
            float p3 = __expf(c[nt][3] - nm1);
            rs0 += p0 + p1; rs1 += p2 + p3;
            c[nt][0] = p0; c[nt][1] = p1; c[nt][2] = p2; c[nt][3] = p3;
        }
        rs0 += __shfl_xor_sync(0xffffffffu, rs0, 1);
        rs0 += __shfl_xor_sync(0xffffffffu, rs0, 2);
        rs1 += __shfl_xor_sync(0xffffffffu, rs1, 1);
        rs1 += __shfl_xor_sync(0xffffffffu, rs1, 2);
        l0r = l0r * sc0 + rs0;
        l1r = l1r * sc1 + rs1;

        #pragma unroll
        for (int nt = 0; nt < 16; nt++) {
            o[nt][0] *= sc0; o[nt][1] *= sc0;
            o[nt][2] *= sc1; o[nt][3] *= sc1;
        }

        // ---- O-GEMM: O += P @ X ; P split inline per s-step
        #pragma unroll
        for (int s = 0; s < 8; s++) {
            uint32_t aH[4], aL[4];
            split2(c[2 * s][0],     c[2 * s][1],     aH[0], aL[0]);
            split2(c[2 * s][2],     c[2 * s][3],     aH[1], aL[1]);
            split2(c[2 * s + 1][0], c[2 * s + 1][1], aH[2], aL[2]);
            split2(c[2 * s + 1][2], c[2 * s + 1][3], aH[3], aL[3]);
            #pragma unroll
            for (int np = 0; np < 8; np++) {
                int brow = s * 16 + rr + ((mat & 1) << 3);   // k = m rows
                int bu   = 2 * np + (mat >> 1);              // n = f cols
                uint32_t baddr = xb + (uint32_t)brow * 256 + ((bu ^ (brow & 7)) << 4);
                uint32_t bh[4], bl[4];
                ldsm4t(bh, baddr);
                ldsm4t(bl, baddr + TILE_B);
                mma16816(o[2 * np],     aH, &bh[0]);
                mma16816(o[2 * np],     aH, &bl[0]);
                mma16816(o[2 * np],     aL, &bh[0]);
                mma16816(o[2 * np + 1], aH, &bh[2]);
                mma16816(o[2 * np + 1], aH, &bl[2]);
                mma16816(o[2 * np + 1], aL, &bh[2]);
            }
        }
    }

    // ---- epilogue: normalize, +bias, elu, store
    const float inv0 = 1.f / l0r, inv1 = 1.f / l1r;
    const int gr0 = row0 + wrow0 + g;
    float* outb = out + (size_t)b * N_DIM * F_DIM;
    #pragma unroll
    for (int nt = 0; nt < 16; nt++) {
        int f = nt * 8 + 2 * t4;
        float bb0 = __ldg(&bias[f]), bb1 = __ldg(&bias[f + 1]);
        float v0 = o[nt][0] * inv0 + bb0; v0 = (v0 > 0.f) ? v0 : expm1f(v0);
        float v1 = o[nt][1] * inv0 + bb1; v1 = (v1 > 0.f) ? v1 : expm1f(v1);
        float v2 = o[nt][2] * inv1 + bb0; v2 = (v2 > 0.f) ? v2 : expm1f(v2);
        float v3 = o[nt][3] * inv1 + bb1; v3 = (v3 > 0.f) ? v3 : expm1f(v3);
        *reinterpret_cast<float2*>(&outb[(size_t)gr0 * F_DIM + f])       = make_float2(v0, v1);
        *reinterpret_cast<float2*>(&outb[(size_t)(gr0 + 8) * F_DIM + f]) = make_float2(v2, v3);
    }
}

// ---------------------------------------------------------------------------
// Launch. Inputs mapped by element count (all four unique):
//   x: 4194304 f32, adj: 67108864 i32, W_a: 16384 f32, bias: 128 f32
// ---------------------------------------------------------------------------
extern "C" void kernel_launch(void* const* d_in, const int* in_sizes, int n_in,
                              void* d_out, int out_size)
{
    (void)out_size;
    const float* x  = nullptr;
    const int*   aj = nullptr;
    const float* W  = nullptr;
    const float* bi = nullptr;
    for (int i = 0; i < n_in; i++) {
        switch (in_sizes[i]) {
            case (int)NELEM:    x  = (const float*)d_in[i]; break;  // 4194304
            case 67108864:      aj = (const int*)  d_in[i]; break;
            case F_DIM * F_DIM: W  = (const float*)d_in[i]; break;  // 16384
            case F_DIM:         bi = (const float*)d_in[i]; break;  // 128
            default: break;
        }
    }
    float* out = (float*)d_out;

    wsplit_kernel<<<F_DIM * F_DIM / 256, 256>>>(W);
    xsplit_kernel<<<(int)(NELEM / 4 / 256), 256>>>(x);

    cudaFuncSetAttribute(gat_mma_kernel, cudaFuncAttributeMaxDynamicSharedMemorySize,
                         SM_TOTAL);
    dim3 grid(N_DIM / 128, B_DIM);   // (16, 16) = 256 blocks
    gat_mma_kernel<<<grid, 256, SM_TOTAL>>>(aj, bi, out);
}